// round 1
// baseline (speedup 1.0000x reference)
#include <cuda_runtime.h>

// ---------------------------------------------------------------------------
// Problem constants (fixed by the reference)
// ---------------------------------------------------------------------------
#define Bsz    2
#define Lseq   1024
#define VOC    32000
#define Dm     512
#define NLAY   2
#define INNER  1024      // mamba inner dim
#define MLPD   2048
#define NSEG   8
#define SEGLEN 128
#define NROWS  (Bsz*Lseq)      // 2048 rows in every GEMM (base AND segment phase)
#define SPLITK 8
#define KCHUNK (VOC/SPLITK)    // 4000

// ---------------------------------------------------------------------------
// Scratch (device globals; no allocation at runtime)
// ---------------------------------------------------------------------------
__device__ float g_x      [NROWS * Dm];               // base activations (starts as `correct`)
__device__ float g_dec    [NROWS * Dm];               // decoder_output @ E
__device__ float g_decpart[SPLITK * NROWS * Dm];      // split-K partials
__device__ float g_ug     [NROWS * 2 * INNER];        // x @ Win  (u | g)
__device__ float g_h      [NROWS * INNER];            // SSM states
__device__ float g_mlp    [NROWS * MLPD];
__device__ float g_xs     [NROWS * Dm];               // segment activations (16 seqs x 128)
__device__ float g_state  [NLAY * Bsz * NSEG * INNER];// h checkpoints at segment starts
__device__ float g_last   [Bsz * NSEG * Dm];
__device__ int   g_starts [Bsz * NSEG];
__device__ int   g_ends   [Bsz * NSEG];

__device__ __forceinline__ float silu_f(float v) { return v * (1.f / (1.f + __expf(-v))); }

// ---------------------------------------------------------------------------
// Workhorse GEMM: C[M,N] (op)= Aop(A)[M,K] * B[K,N]
//   128x128 block tile, BK=8, 256 threads, 8x8 per-thread microtile, fp32.
//   AMODE 0: a = A[r,k]
//   AMODE 1: a = silu(A[r,k]) * A2[r,k]      (gated SSM output for Wout GEMM)
//   EPI   0: C = acc          (store; per-splitK slice via blockIdx.z)
//   EPI   1: C = silu(acc)
//   EPI   2: C += acc         (residual)
//  Requires M%128==0, N%128==0, kchunk%8==0 (all hold here).
// ---------------------------------------------------------------------------
#define BMt 128
#define BNt 128
#define BKt 8

template<int AMODE, int EPI>
__global__ void __launch_bounds__(256, 2)
gemm_tile(const float* __restrict__ A, const float* __restrict__ A2,
          const float* __restrict__ Bm, float* __restrict__ C,
          int lda, int lda2, int ldb, int ldc, int kchunk, int cslice)
{
    __shared__ float As[BKt][BMt];
    __shared__ float Bs[BKt][BNt];

    const int tid = threadIdx.x;
    const int tx = tid & 15, ty = tid >> 4;
    const int rowBase = blockIdx.y * BMt;
    const int colBase = blockIdx.x * BNt;
    const int ar = tid >> 1, ac = (tid & 1) << 2;   // A tile: 128 rows x 8 k (2 f4/row)
    const int br = tid >> 5, bc = (tid & 31) << 2;  // B tile: 8 k x 128 cols
    const int kbeg = blockIdx.z * kchunk;

    float acc[8][8];
#pragma unroll
    for (int i = 0; i < 8; i++)
#pragma unroll
        for (int j = 0; j < 8; j++) acc[i][j] = 0.f;

    for (int k0 = kbeg; k0 < kbeg + kchunk; k0 += BKt) {
        float4 av;
        {
            const float4 a4 = *(const float4*)(A + (size_t)(rowBase + ar) * lda + k0 + ac);
            if (AMODE == 0) {
                av = a4;
            } else {
                const float4 h4 = *(const float4*)(A2 + (size_t)(rowBase + ar) * lda2 + k0 + ac);
                av.x = silu_f(a4.x) * h4.x; av.y = silu_f(a4.y) * h4.y;
                av.z = silu_f(a4.z) * h4.z; av.w = silu_f(a4.w) * h4.w;
            }
        }
        const float4 bv = *(const float4*)(Bm + (size_t)(k0 + br) * ldb + colBase + bc);

        __syncthreads();   // previous tile's compute done reading smem
        As[ac + 0][ar] = av.x; As[ac + 1][ar] = av.y;
        As[ac + 2][ar] = av.z; As[ac + 3][ar] = av.w;
        *(float4*)&Bs[br][bc] = bv;
        __syncthreads();

#pragma unroll
        for (int kk = 0; kk < BKt; kk++) {
            float ra[8], rb[8];
            *(float4*)&ra[0] = *(const float4*)&As[kk][ty * 8];
            *(float4*)&ra[4] = *(const float4*)&As[kk][ty * 8 + 4];
            *(float4*)&rb[0] = *(const float4*)&Bs[kk][tx * 8];
            *(float4*)&rb[4] = *(const float4*)&Bs[kk][tx * 8 + 4];
#pragma unroll
            for (int i = 0; i < 8; i++)
#pragma unroll
                for (int j = 0; j < 8; j++) acc[i][j] = fmaf(ra[i], rb[j], acc[i][j]);
        }
    }

    float* Cb = C + (size_t)blockIdx.z * cslice;
#pragma unroll
    for (int i = 0; i < 8; i++) {
        const int r = rowBase + ty * 8 + i;
        float* crow = Cb + (size_t)r * ldc + colBase + tx * 8;
#pragma unroll
        for (int j = 0; j < 8; j += 4) {
            float4 v = make_float4(acc[i][j], acc[i][j+1], acc[i][j+2], acc[i][j+3]);
            if (EPI == 1) { v.x = silu_f(v.x); v.y = silu_f(v.y); v.z = silu_f(v.z); v.w = silu_f(v.w); }
            if (EPI == 2) { float4 o = *(float4*)(crow + j); v.x += o.x; v.y += o.y; v.z += o.z; v.w += o.w; }
            *(float4*)(crow + j) = v;
        }
    }
}

// ---------------------------------------------------------------------------
// Small kernels
// ---------------------------------------------------------------------------
__global__ void compute_starts_k(const int* __restrict__ seg, int* __restrict__ starts,
                                 int* __restrict__ ends)
{
    int b = threadIdx.x;
    if (b >= Bsz) return;
    int cnt = 0;
    for (int t = 0; t < Lseq && cnt < NSEG; t++)
        if (seg[b * Lseq + t] != 0) starts[b * NSEG + cnt++] = t;
    while (cnt < NSEG) { starts[b * NSEG + cnt] = 0; cnt++; }
    for (int i = 0; i < NSEG - 1; i++) ends[b * NSEG + i] = starts[b * NSEG + i + 1];
    ends[b * NSEG + NSEG - 1] = Lseq;
}

__global__ void gather_correct_k(const int* __restrict__ ids, const float* __restrict__ E,
                                 float* __restrict__ x)
{
    const int row = blockIdx.x;                      // 0..2047
    const int id = ids[row];
    const float4* s = (const float4*)(E + (size_t)id * Dm);
    float4* d = (float4*)(x + (size_t)row * Dm);
    d[threadIdx.x] = s[threadIdx.x];                 // 128 threads * f4 = 512 floats
}

__global__ void reduce_dec_k(const float* __restrict__ part, float* __restrict__ dec)
{
    const int i = blockIdx.x * blockDim.x + threadIdx.x;  // < NROWS*Dm
    float s = 0.f;
#pragma unroll
    for (int p = 0; p < SPLITK; p++) s += part[(size_t)p * NROWS * Dm + i];
    dec[i] = s;
}

// Per-channel sequential linear recurrence: h_t = a*h_{t-1} + u_t.
// One thread per (sequence, channel). u = first INNER columns of ug.
__global__ void recurrence_k(const float* __restrict__ ug, const float* __restrict__ Avec,
                             float* __restrict__ h, const float* __restrict__ init, int seqlen)
{
    const int idx = blockIdx.x * blockDim.x + threadIdx.x;
    const int q = idx >> 10;          // sequence index
    const int c = idx & (INNER - 1);  // channel
    const float a = Avec[c];
    const float* up = ug + (size_t)q * seqlen * (2 * INNER) + c;
    float* hp = h + (size_t)q * seqlen * INNER + c;
    float hv = init ? init[idx] : 0.f;
    for (int t = 0; t < seqlen; t++) {
        hv = fmaf(a, hv, up[(size_t)t * (2 * INNER)]);
        hp[(size_t)t * INNER] = hv;
    }
}

// Checkpoint base-run state at each segment start: state[b,i] = h_base[b, s_i - 1]  (0 if s_i==0)
__global__ void save_state_k(const float* __restrict__ h, float* __restrict__ st,
                             const int* __restrict__ starts)
{
    const int r = blockIdx.x;         // b*NSEG+i  (16)
    const int c = threadIdx.x;        // 1024
    const int b = r >> 3;
    const int s = starts[r];
    st[(size_t)r * INNER + c] = (s > 0) ? h[((size_t)b * Lseq + (s - 1)) * INNER + c] : 0.f;
}

// Segment inputs: xs[b,i,t,:] = dec[b, s_i + t, :]  (zero past end)
__global__ void build_xs_k(const float* __restrict__ dec, float* __restrict__ xs,
                           const int* __restrict__ starts, const int* __restrict__ ends)
{
    const int r = blockIdx.x;         // 0..2047
    const int q = r >> 7;             // seq index 0..15
    const int t = r & (SEGLEN - 1);
    const int b = q >> 3;
    const int s = starts[q], e = ends[q];
    const int pos = s + t;
    float4 v = make_float4(0.f, 0.f, 0.f, 0.f);
    if (pos < e && pos < Lseq)
        v = ((const float4*)(dec + ((size_t)b * Lseq + pos) * Dm))[threadIdx.x];
    ((float4*)(xs + (size_t)r * Dm))[threadIdx.x] = v;
}

__global__ void extract_last_k(const float* __restrict__ xs, float* __restrict__ last,
                               const int* __restrict__ starts, const int* __restrict__ ends)
{
    const int q = blockIdx.x;         // 16
    int len = ends[q] - starts[q];
    if (len > SEGLEN) len = SEGLEN;
    if (len < 1) len = 1;
    const float4* s = (const float4*)(xs + ((size_t)q * SEGLEN + (len - 1)) * Dm);
    float4* d = (float4*)(last + (size_t)q * Dm);
    d[threadIdx.x] = s[threadIdx.x];
}

// mu_q / logvar_q heads: out[0:8192] = mu, out[8192:16384] = logvar
__global__ void head_k(const float* __restrict__ last,
                       const float* __restrict__ muW, const float* __restrict__ mub,
                       const float* __restrict__ lvW, const float* __restrict__ lvb,
                       float* __restrict__ out)
{
    const int o = blockIdx.x * blockDim.x + threadIdx.x;   // < 16384
    const int which = o >> 13;
    const int rem = o & 8191;
    const int r = rem >> 9, d = rem & 511;
    const float* W = which ? lvW : muW;
    const float* bias = which ? lvb : mub;
    const float* lr = last + (size_t)r * Dm;
    float acc = bias[d];
#pragma unroll 8
    for (int k = 0; k < Dm; k++) acc = fmaf(lr[k], W[(size_t)k * Dm + d], acc);
    out[o] = acc;
}

// ---------------------------------------------------------------------------
// Orchestration
// ---------------------------------------------------------------------------
extern "C" void kernel_launch(void* const* d_in, const int* in_sizes, int n_in,
                              void* d_out, int out_size)
{
    const float* decoder_output = (const float*)d_in[0];
    const int*   input_ids      = (const int*)  d_in[1];
    const int*   seg_idx        = (const int*)  d_in[2];
    const float* E              = (const float*)d_in[3];
    const float* Aparam         = (const float*)d_in[4];
    const float* Win            = (const float*)d_in[5];
    const float* Wout           = (const float*)d_in[6];
    const float* Wm1            = (const float*)d_in[7];
    const float* Wm2            = (const float*)d_in[8];
    const float* muW            = (const float*)d_in[9];
    const float* mub            = (const float*)d_in[10];
    const float* lvW            = (const float*)d_in[11];
    const float* lvb            = (const float*)d_in[12];
    float* out = (float*)d_out;

    float *x, *dec, *decpart, *ug, *h, *mlp, *xs, *state, *last;
    int *starts, *ends;
    cudaGetSymbolAddress((void**)&x,       g_x);
    cudaGetSymbolAddress((void**)&dec,     g_dec);
    cudaGetSymbolAddress((void**)&decpart, g_decpart);
    cudaGetSymbolAddress((void**)&ug,      g_ug);
    cudaGetSymbolAddress((void**)&h,       g_h);
    cudaGetSymbolAddress((void**)&mlp,     g_mlp);
    cudaGetSymbolAddress((void**)&xs,      g_xs);
    cudaGetSymbolAddress((void**)&state,   g_state);
    cudaGetSymbolAddress((void**)&last,    g_last);
    cudaGetSymbolAddress((void**)&starts,  g_starts);
    cudaGetSymbolAddress((void**)&ends,    g_ends);

    // Segment boundaries + ground-truth embeddings
    compute_starts_k<<<1, 32>>>(seg_idx, starts, ends);
    gather_correct_k<<<NROWS, 128>>>(input_ids, E, x);

    // dec = decoder_output @ E  (split-K over 32000)
    gemm_tile<0, 0><<<dim3(Dm / BNt, NROWS / BMt, SPLITK), 256>>>(
        decoder_output, nullptr, E, decpart, VOC, 0, Dm, Dm, KCHUNK, NROWS * Dm);
    reduce_dec_k<<<(NROWS * Dm) / 256, 256>>>(decpart, dec);

    // -------- Base pass: full-length `correct` sequences, checkpoint SSM states --------
    for (int l = 0; l < NLAY; l++) {
        const float* Winl  = Win  + (size_t)l * Dm * 2 * INNER;
        const float* Woutl = Wout + (size_t)l * INNER * Dm;
        const float* Wm1l  = Wm1  + (size_t)l * Dm * MLPD;
        const float* Wm2l  = Wm2  + (size_t)l * MLPD * Dm;
        const float* Al    = Aparam + (size_t)l * INNER;
        float* stl = state + (size_t)l * Bsz * NSEG * INNER;

        gemm_tile<0, 0><<<dim3((2 * INNER) / BNt, NROWS / BMt, 1), 256>>>(
            x, nullptr, Winl, ug, Dm, 0, 2 * INNER, 2 * INNER, Dm, 0);
        recurrence_k<<<(Bsz * INNER) / 256, 256>>>(ug, Al, h, nullptr, Lseq);
        save_state_k<<<Bsz * NSEG, INNER>>>(h, stl, starts);
        gemm_tile<1, 2><<<dim3(Dm / BNt, NROWS / BMt, 1), 256>>>(
            ug + INNER, h, Woutl, x, 2 * INNER, INNER, Dm, Dm, INNER, 0);
        gemm_tile<0, 1><<<dim3(MLPD / BNt, NROWS / BMt, 1), 256>>>(
            x, nullptr, Wm1l, mlp, Dm, 0, MLPD, MLPD, Dm, 0);
        gemm_tile<0, 2><<<dim3(Dm / BNt, NROWS / BMt, 1), 256>>>(
            mlp, nullptr, Wm2l, x, MLPD, 0, Dm, Dm, MLPD, 0);
    }

    // -------- Segment pass: 16 independent 128-token sequences from saved states --------
    build_xs_k<<<NROWS, 128>>>(dec, xs, starts, ends);
    for (int l = 0; l < NLAY; l++) {
        const float* Winl  = Win  + (size_t)l * Dm * 2 * INNER;
        const float* Woutl = Wout + (size_t)l * INNER * Dm;
        const float* Wm1l  = Wm1  + (size_t)l * Dm * MLPD;
        const float* Wm2l  = Wm2  + (size_t)l * MLPD * Dm;
        const float* Al    = Aparam + (size_t)l * INNER;
        const float* stl = state + (size_t)l * Bsz * NSEG * INNER;

        gemm_tile<0, 0><<<dim3((2 * INNER) / BNt, NROWS / BMt, 1), 256>>>(
            xs, nullptr, Winl, ug, Dm, 0, 2 * INNER, 2 * INNER, Dm, 0);
        recurrence_k<<<(Bsz * NSEG * INNER) / 256, 256>>>(ug, Al, h, stl, SEGLEN);
        gemm_tile<1, 2><<<dim3(Dm / BNt, NROWS / BMt, 1), 256>>>(
            ug + INNER, h, Woutl, xs, 2 * INNER, INNER, Dm, Dm, INNER, 0);
        gemm_tile<0, 1><<<dim3(MLPD / BNt, NROWS / BMt, 1), 256>>>(
            xs, nullptr, Wm1l, mlp, Dm, 0, MLPD, MLPD, Dm, 0);
        gemm_tile<0, 2><<<dim3(Dm / BNt, NROWS / BMt, 1), 256>>>(
            mlp, nullptr, Wm2l, xs, MLPD, 0, Dm, Dm, MLPD, 0);
    }

    extract_last_k<<<Bsz * NSEG, 128>>>(xs, last, starts, ends);
    head_k<<<(2 * Bsz * NSEG * Dm) / 256, 256>>>(last, muW, mub, lvW, lvb, out);
}

// round 3
// speedup vs baseline: 2.5190x; 2.5190x over previous
#include <cuda_runtime.h>
#include <cuda_bf16.h>
#include <cstdint>

// ---------------------------------------------------------------------------
// Problem constants
// ---------------------------------------------------------------------------
#define Bsz    2
#define Lseq   1024
#define VOC    32000
#define Dm     512
#define NLAY   2
#define INNER  1024
#define MLPD   2048
#define NSEG   8
#define SEGLEN 128
#define NROWS  (Bsz*Lseq)      // 2048
#define DEC_SK 8
#define DEC_KSLICE (VOC/DEC_SK)   // 4000

// ---------------------------------------------------------------------------
// Scratch
// ---------------------------------------------------------------------------
__device__ float g_x      [NROWS * Dm];
__device__ float g_dec    [NROWS * Dm];
__device__ float g_decpart[DEC_SK * NROWS * Dm];
__device__ float g_ug     [NROWS * 2 * INNER];
__device__ float g_h      [NROWS * INNER];
__device__ float g_mlp    [NROWS * MLPD];
__device__ float g_xs     [NROWS * Dm];
__device__ float g_state  [NLAY * Bsz * NSEG * INNER];
__device__ float g_last   [Bsz * NSEG * Dm];
__device__ int   g_starts [Bsz * NSEG];
__device__ int   g_ends   [Bsz * NSEG];
// bf16 hi/lo pre-splits (B operands, stored [K, N] row-major like the fp32 originals)
__device__ __nv_bfloat16 g_Eh   [VOC * Dm];
__device__ __nv_bfloat16 g_El   [VOC * Dm];
__device__ __nv_bfloat16 g_WinH [NLAY * Dm * 2 * INNER];
__device__ __nv_bfloat16 g_WinL [NLAY * Dm * 2 * INNER];
__device__ __nv_bfloat16 g_WoutH[NLAY * INNER * Dm];
__device__ __nv_bfloat16 g_WoutL[NLAY * INNER * Dm];
__device__ __nv_bfloat16 g_Wm1H [NLAY * Dm * MLPD];
__device__ __nv_bfloat16 g_Wm1L [NLAY * Dm * MLPD];
__device__ __nv_bfloat16 g_Wm2H [NLAY * MLPD * Dm];
__device__ __nv_bfloat16 g_Wm2L [NLAY * MLPD * Dm];

__device__ __forceinline__ float silu_f(float v) { return v * (1.f / (1.f + __expf(-v))); }

// bf16 hi/lo split of two floats, packed as bf16x2 words
__device__ __forceinline__ void split2(float a, float b, uint32_t& hp, uint32_t& lp) {
    __nv_bfloat16 ah = __float2bfloat16(a), bh = __float2bfloat16(b);
    float ar = a - __bfloat162float(ah), br = b - __bfloat162float(bh);
    __nv_bfloat16 al = __float2bfloat16(ar), bl = __float2bfloat16(br);
    hp = (uint32_t)__bfloat16_as_ushort(ah) | ((uint32_t)__bfloat16_as_ushort(bh) << 16);
    lp = (uint32_t)__bfloat16_as_ushort(al) | ((uint32_t)__bfloat16_as_ushort(bl) << 16);
}

// ---------------------------------------------------------------------------
// mma.sync / ldmatrix primitives (arch-generic, sm_80+)
// ---------------------------------------------------------------------------
__device__ __forceinline__ uint32_t smem_u32(const void* p) {
    return (uint32_t)__cvta_generic_to_shared(p);
}

__device__ __forceinline__ void ldmA(uint32_t* r, uint32_t addr) {
    asm volatile("ldmatrix.sync.aligned.m8n8.x4.shared.b16 {%0,%1,%2,%3}, [%4];"
                 : "=r"(r[0]), "=r"(r[1]), "=r"(r[2]), "=r"(r[3]) : "r"(addr));
}

__device__ __forceinline__ void ldmT(uint32_t& r0, uint32_t& r1, uint32_t& r2, uint32_t& r3,
                                     uint32_t addr) {
    asm volatile("ldmatrix.sync.aligned.m8n8.x4.trans.shared.b16 {%0,%1,%2,%3}, [%4];"
                 : "=r"(r0), "=r"(r1), "=r"(r2), "=r"(r3) : "r"(addr));
}

__device__ __forceinline__ void mma16816(float* c, const uint32_t* a, const uint32_t* b) {
    asm volatile("mma.sync.aligned.m16n8k16.row.col.f32.bf16.bf16.f32 "
                 "{%0,%1,%2,%3}, {%4,%5,%6,%7}, {%8,%9}, {%0,%1,%2,%3};"
                 : "+f"(c[0]), "+f"(c[1]), "+f"(c[2]), "+f"(c[3])
                 : "r"(a[0]), "r"(a[1]), "r"(a[2]), "r"(a[3]), "r"(b[0]), "r"(b[1]));
}

// ---------------------------------------------------------------------------
// Unified tensor-core GEMM: C[M,N] (op)= Aop(A)[M,K] * B[K,N]
//   fp32 A split on the fly to bf16 hi/lo; B pre-split hi/lo.
//   3-term emulation: AhBh + AlBh + AhBl  (fp32-accurate to ~2^-17)
//   CTA tile 128x128x32, 8 warps (2 m x 4 n), warp tile 64x32, m16n8k16.
//   AMODE 0: a = A[r,k] ; AMODE 1: a = silu(A[r,k]) * A2[r,k]
//   EPI 0: C = acc ; EPI 1: C = silu(acc) ; EPI 2: C += acc
//   Requires M%128==0, N%128==0, kchunk%32==0.
// ---------------------------------------------------------------------------
#define A_LD 40     // 32 k + 8 pad (bf16) -> 80B rows, ldmatrix conflict-free
#define B_LD 136    // 128 n + 8 pad      -> 272B rows, conflict-free

template<int AMODE, int EPI>
__global__ void __launch_bounds__(256)
gemm_mma(const float* __restrict__ A, const float* __restrict__ A2,
         const __nv_bfloat16* __restrict__ Bh, const __nv_bfloat16* __restrict__ Bl,
         float* __restrict__ C,
         int lda, int lda2, int ldb, int ldc, int kchunk, int cslice)
{
    __shared__ __align__(16) __nv_bfloat16 sAh[128 * A_LD];
    __shared__ __align__(16) __nv_bfloat16 sAl[128 * A_LD];
    __shared__ __align__(16) __nv_bfloat16 sBh[32 * B_LD];
    __shared__ __align__(16) __nv_bfloat16 sBl[32 * B_LD];

    const int tid  = threadIdx.x;
    const int lane = tid & 31;
    const int wid  = tid >> 5;
    const int wm = (wid & 1) * 64;        // warp row base in CTA tile
    const int wn = (wid >> 1) * 32;       // warp col base
    const int mbase = blockIdx.y * 128;
    const int nbase = blockIdx.x * 128;
    const int kbeg  = blockIdx.z * kchunk;

    float acc[4][4][4];
#pragma unroll
    for (int i = 0; i < 4; i++)
#pragma unroll
        for (int j = 0; j < 4; j++)
#pragma unroll
            for (int f = 0; f < 4; f++) acc[i][j][f] = 0.f;

    // thread->tile mapping for global loads
    const int arow = tid >> 3, ac4 = tid & 7;      // A: 4 slots of (row, 4-float col)
    const int brow = tid >> 4, bc8 = tid & 15;     // B: 2 slots of (k-row, 8-bf16 col)

    for (int k0 = kbeg; k0 < kbeg + kchunk; k0 += 32) {
        float4 a[4], g2[4];
        uint4 vbh[2], vbl[2];
#pragma unroll
        for (int i = 0; i < 4; i++) {
            const int r = arow + i * 32;
            a[i] = *(const float4*)(A + (size_t)(mbase + r) * lda + k0 + ac4 * 4);
            if (AMODE == 1)
                g2[i] = *(const float4*)(A2 + (size_t)(mbase + r) * lda2 + k0 + ac4 * 4);
        }
#pragma unroll
        for (int i = 0; i < 2; i++) {
            const int r = brow + i * 16;
            const size_t gb = (size_t)(k0 + r) * ldb + nbase + bc8 * 8;
            vbh[i] = *(const uint4*)(Bh + gb);
            vbl[i] = *(const uint4*)(Bl + gb);
        }

        __syncthreads();   // all warps done computing on previous smem contents
#pragma unroll
        for (int i = 0; i < 4; i++) {
            const int r = arow + i * 32;
            float4 v = a[i];
            if (AMODE == 1) {
                v.x = silu_f(v.x) * g2[i].x; v.y = silu_f(v.y) * g2[i].y;
                v.z = silu_f(v.z) * g2[i].z; v.w = silu_f(v.w) * g2[i].w;
            }
            uint32_t h0, l0, h1, l1;
            split2(v.x, v.y, h0, l0);
            split2(v.z, v.w, h1, l1);
            *(uint2*)(sAh + r * A_LD + ac4 * 4) = make_uint2(h0, h1);
            *(uint2*)(sAl + r * A_LD + ac4 * 4) = make_uint2(l0, l1);
        }
#pragma unroll
        for (int i = 0; i < 2; i++) {
            const int r = brow + i * 16;
            *(uint4*)(sBh + r * B_LD + bc8 * 8) = vbh[i];
            *(uint4*)(sBl + r * B_LD + bc8 * 8) = vbl[i];
        }
        __syncthreads();

#pragma unroll
        for (int ks = 0; ks < 32; ks += 16) {
            uint32_t Af[4][4], Alf[4][4];
#pragma unroll
            for (int mt = 0; mt < 4; mt++) {
                const int off = (wm + mt * 16 + (lane & 15)) * A_LD + ks + (lane >> 4) * 8;
                ldmA(Af[mt],  smem_u32(sAh + off));
                ldmA(Alf[mt], smem_u32(sAl + off));
            }
            uint32_t Bf[4][2], Blf[4][2];
#pragma unroll
            for (int g = 0; g < 2; g++) {
                const int off = (ks + (lane & 15)) * B_LD + wn + g * 16 + (lane >> 4) * 8;
                ldmT(Bf[2*g][0], Bf[2*g][1], Bf[2*g+1][0], Bf[2*g+1][1], smem_u32(sBh + off));
                ldmT(Blf[2*g][0], Blf[2*g][1], Blf[2*g+1][0], Blf[2*g+1][1], smem_u32(sBl + off));
            }
#pragma unroll
            for (int mt = 0; mt < 4; mt++)
#pragma unroll
                for (int nt = 0; nt < 4; nt++) {
                    mma16816(acc[mt][nt], Af[mt],  Bf[nt]);
                    mma16816(acc[mt][nt], Alf[mt], Bf[nt]);
                    mma16816(acc[mt][nt], Af[mt],  Blf[nt]);
                }
        }
    }

    // epilogue
    float* Cb = C + (size_t)blockIdx.z * cslice;
    const int tr = lane >> 2, tc = (lane & 3) * 2;
#pragma unroll
    for (int mt = 0; mt < 4; mt++) {
#pragma unroll
        for (int nt = 0; nt < 4; nt++) {
            const int row = mbase + wm + mt * 16 + tr;
            const int col = nbase + wn + nt * 8 + tc;
            float2 v0 = make_float2(acc[mt][nt][0], acc[mt][nt][1]);
            float2 v1 = make_float2(acc[mt][nt][2], acc[mt][nt][3]);
            float* p0 = Cb + (size_t)row * ldc + col;
            float* p1 = Cb + (size_t)(row + 8) * ldc + col;
            if (EPI == 1) {
                v0.x = silu_f(v0.x); v0.y = silu_f(v0.y);
                v1.x = silu_f(v1.x); v1.y = silu_f(v1.y);
            }
            if (EPI == 2) {
                float2 o0 = *(float2*)p0, o1 = *(float2*)p1;
                v0.x += o0.x; v0.y += o0.y; v1.x += o1.x; v1.y += o1.y;
            }
            *(float2*)p0 = v0;
            *(float2*)p1 = v1;
        }
    }
}

// ---------------------------------------------------------------------------
// fp32 -> bf16 hi/lo split (elementwise, vectorized)
// ---------------------------------------------------------------------------
__global__ void split_k(const float* __restrict__ src,
                        __nv_bfloat16* __restrict__ hi, __nv_bfloat16* __restrict__ lo, int n4)
{
    const int i = blockIdx.x * blockDim.x + threadIdx.x;
    if (i >= n4) return;
    const float4 v = ((const float4*)src)[i];
    uint32_t h0, l0, h1, l1;
    split2(v.x, v.y, h0, l0);
    split2(v.z, v.w, h1, l1);
    ((uint2*)hi)[i] = make_uint2(h0, h1);
    ((uint2*)lo)[i] = make_uint2(l0, l1);
}

// ---------------------------------------------------------------------------
// Small kernels
// ---------------------------------------------------------------------------
__global__ void compute_starts_k(const int* __restrict__ seg, int* __restrict__ starts,
                                 int* __restrict__ ends)
{
    int b = threadIdx.x;
    if (b >= Bsz) return;
    int cnt = 0;
    for (int t = 0; t < Lseq && cnt < NSEG; t++)
        if (seg[b * Lseq + t] != 0) starts[b * NSEG + cnt++] = t;
    while (cnt < NSEG) { starts[b * NSEG + cnt] = 0; cnt++; }
    for (int i = 0; i < NSEG - 1; i++) ends[b * NSEG + i] = starts[b * NSEG + i + 1];
    ends[b * NSEG + NSEG - 1] = Lseq;
}

__global__ void gather_correct_k(const int* __restrict__ ids, const float* __restrict__ E,
                                 float* __restrict__ x)
{
    const int row = blockIdx.x;
    const int id = ids[row];
    const float4* s = (const float4*)(E + (size_t)id * Dm);
    float4* d = (float4*)(x + (size_t)row * Dm);
    d[threadIdx.x] = s[threadIdx.x];
}

__global__ void reduce_dec_k(const float* __restrict__ part, float* __restrict__ dec)
{
    const int i = blockIdx.x * blockDim.x + threadIdx.x;
    float s = 0.f;
#pragma unroll
    for (int p = 0; p < DEC_SK; p++) s += part[(size_t)p * NROWS * Dm + i];
    dec[i] = s;
}

__global__ void recurrence_k(const float* __restrict__ ug, const float* __restrict__ Avec,
                             float* __restrict__ h, const float* __restrict__ init, int seqlen)
{
    const int idx = blockIdx.x * blockDim.x + threadIdx.x;
    const int q = idx >> 10;
    const int c = idx & (INNER - 1);
    const float a = Avec[c];
    const float* up = ug + (size_t)q * seqlen * (2 * INNER) + c;
    float* hp = h + (size_t)q * seqlen * INNER + c;
    float hv = init ? init[idx] : 0.f;
    for (int t = 0; t < seqlen; t++) {
        hv = fmaf(a, hv, up[(size_t)t * (2 * INNER)]);
        hp[(size_t)t * INNER] = hv;
    }
}

__global__ void save_state_k(const float* __restrict__ h, float* __restrict__ st,
                             const int* __restrict__ starts)
{
    const int r = blockIdx.x;
    const int c = threadIdx.x;
    const int b = r >> 3;
    const int s = starts[r];
    st[(size_t)r * INNER + c] = (s > 0) ? h[((size_t)b * Lseq + (s - 1)) * INNER + c] : 0.f;
}

__global__ void build_xs_k(const float* __restrict__ dec, float* __restrict__ xs,
                           const int* __restrict__ starts, const int* __restrict__ ends)
{
    const int r = blockIdx.x;
    const int q = r >> 7;
    const int t = r & (SEGLEN - 1);
    const int b = q >> 3;
    const int s = starts[q], e = ends[q];
    const int pos = s + t;
    float4 v = make_float4(0.f, 0.f, 0.f, 0.f);
    if (pos < e && pos < Lseq)
        v = ((const float4*)(dec + ((size_t)b * Lseq + pos) * Dm))[threadIdx.x];
    ((float4*)(xs + (size_t)r * Dm))[threadIdx.x] = v;
}

__global__ void extract_last_k(const float* __restrict__ xs, float* __restrict__ last,
                               const int* __restrict__ starts, const int* __restrict__ ends)
{
    const int q = blockIdx.x;
    int len = ends[q] - starts[q];
    if (len > SEGLEN) len = SEGLEN;
    if (len < 1) len = 1;
    const float4* s = (const float4*)(xs + ((size_t)q * SEGLEN + (len - 1)) * Dm);
    float4* d = (float4*)(last + (size_t)q * Dm);
    d[threadIdx.x] = s[threadIdx.x];
}

__global__ void head_k(const float* __restrict__ last,
                       const float* __restrict__ muW, const float* __restrict__ mub,
                       const float* __restrict__ lvW, const float* __restrict__ lvb,
                       float* __restrict__ out)
{
    const int o = blockIdx.x * blockDim.x + threadIdx.x;
    const int which = o >> 13;
    const int rem = o & 8191;
    const int r = rem >> 9, d = rem & 511;
    const float* W = which ? lvW : muW;
    const float* bias = which ? lvb : mub;
    const float* lr = last + (size_t)r * Dm;
    float acc = bias[d];
#pragma unroll 8
    for (int k = 0; k < Dm; k++) acc = fmaf(lr[k], W[(size_t)k * Dm + d], acc);
    out[o] = acc;
}

// ---------------------------------------------------------------------------
// Orchestration
// ---------------------------------------------------------------------------
extern "C" void kernel_launch(void* const* d_in, const int* in_sizes, int n_in,
                              void* d_out, int out_size)
{
    const float* decoder_output = (const float*)d_in[0];
    const int*   input_ids      = (const int*)  d_in[1];
    const int*   seg_idx        = (const int*)  d_in[2];
    const float* E              = (const float*)d_in[3];
    const float* Aparam         = (const float*)d_in[4];
    const float* Win            = (const float*)d_in[5];
    const float* Wout           = (const float*)d_in[6];
    const float* Wm1            = (const float*)d_in[7];
    const float* Wm2            = (const float*)d_in[8];
    const float* muW            = (const float*)d_in[9];
    const float* mub            = (const float*)d_in[10];
    const float* lvW            = (const float*)d_in[11];
    const float* lvb            = (const float*)d_in[12];
    float* out = (float*)d_out;

    float *x, *dec, *decpart, *ug, *h, *mlp, *xs, *state, *last;
    int *starts, *ends;
    __nv_bfloat16 *eh, *el, *winh, *winl, *wouth, *woutl, *wm1h, *wm1l, *wm2h, *wm2l;
    cudaGetSymbolAddress((void**)&x,       g_x);
    cudaGetSymbolAddress((void**)&dec,     g_dec);
    cudaGetSymbolAddress((void**)&decpart, g_decpart);
    cudaGetSymbolAddress((void**)&ug,      g_ug);
    cudaGetSymbolAddress((void**)&h,       g_h);
    cudaGetSymbolAddress((void**)&mlp,     g_mlp);
    cudaGetSymbolAddress((void**)&xs,      g_xs);
    cudaGetSymbolAddress((void**)&state,   g_state);
    cudaGetSymbolAddress((void**)&last,    g_last);
    cudaGetSymbolAddress((void**)&starts,  g_starts);
    cudaGetSymbolAddress((void**)&ends,    g_ends);
    cudaGetSymbolAddress((void**)&eh,      g_Eh);
    cudaGetSymbolAddress((void**)&el,      g_El);
    cudaGetSymbolAddress((void**)&winh,    g_WinH);
    cudaGetSymbolAddress((void**)&winl,    g_WinL);
    cudaGetSymbolAddress((void**)&wouth,   g_WoutH);
    cudaGetSymbolAddress((void**)&woutl,   g_WoutL);
    cudaGetSymbolAddress((void**)&wm1h,    g_Wm1H);
    cudaGetSymbolAddress((void**)&wm1l,    g_Wm1L);
    cudaGetSymbolAddress((void**)&wm2h,    g_Wm2H);
    cudaGetSymbolAddress((void**)&wm2l,    g_Wm2L);

    // Pre-split B operands to bf16 hi/lo
    auto split = [&](const float* s, __nv_bfloat16* hh, __nv_bfloat16* ll, int n) {
        split_k<<<(n / 4 + 255) / 256, 256>>>(s, hh, ll, n / 4);
    };
    split(E,    eh,    el,    VOC * Dm);
    split(Win,  winh,  winl,  NLAY * Dm * 2 * INNER);
    split(Wout, wouth, woutl, NLAY * INNER * Dm);
    split(Wm1,  wm1h,  wm1l,  NLAY * Dm * MLPD);
    split(Wm2,  wm2h,  wm2l,  NLAY * MLPD * Dm);

    compute_starts_k<<<1, 32>>>(seg_idx, starts, ends);
    gather_correct_k<<<NROWS, 128>>>(input_ids, E, x);

    // dec = decoder_output @ E  (tensor cores, bf16x3, split-K=8)
    gemm_mma<0, 0><<<dim3(Dm / 128, NROWS / 128, DEC_SK), 256>>>(
        decoder_output, nullptr, eh, el, decpart, VOC, 0, Dm, Dm, DEC_KSLICE, NROWS * Dm);
    reduce_dec_k<<<(NROWS * Dm) / 256, 256>>>(decpart, dec);

    // -------- Base pass: full-length `correct` sequences, checkpoint SSM states --------
    for (int l = 0; l < NLAY; l++) {
        const size_t oWin  = (size_t)l * Dm * 2 * INNER;
        const size_t oWout = (size_t)l * INNER * Dm;
        const size_t oWm1  = (size_t)l * Dm * MLPD;
        const size_t oWm2  = (size_t)l * MLPD * Dm;
        const float* Al    = Aparam + (size_t)l * INNER;
        float* stl = state + (size_t)l * Bsz * NSEG * INNER;

        gemm_mma<0, 0><<<dim3((2 * INNER) / 128, NROWS / 128, 1), 256>>>(
            x, nullptr, winh + oWin, winl + oWin, ug, Dm, 0, 2 * INNER, 2 * INNER, Dm, 0);
        recurrence_k<<<(Bsz * INNER) / 256, 256>>>(ug, Al, h, nullptr, Lseq);
        save_state_k<<<Bsz * NSEG, INNER>>>(h, stl, starts);
        gemm_mma<1, 2><<<dim3(Dm / 128, NROWS / 128, 1), 256>>>(
            ug + INNER, h, wouth + oWout, woutl + oWout, x, 2 * INNER, INNER, Dm, Dm, INNER, 0);
        gemm_mma<0, 1><<<dim3(MLPD / 128, NROWS / 128, 1), 256>>>(
            x, nullptr, wm1h + oWm1, wm1l + oWm1, mlp, Dm, 0, MLPD, MLPD, Dm, 0);
        gemm_mma<0, 2><<<dim3(Dm / 128, NROWS / 128, 1), 256>>>(
            mlp, nullptr, wm2h + oWm2, wm2l + oWm2, x, MLPD, 0, Dm, Dm, MLPD, 0);
    }

    // -------- Segment pass: 16 independent 128-token sequences from saved states --------
    build_xs_k<<<NROWS, 128>>>(dec, xs, starts, ends);
    for (int l = 0; l < NLAY; l++) {
        const size_t oWin  = (size_t)l * Dm * 2 * INNER;
        const size_t oWout = (size_t)l * INNER * Dm;
        const size_t oWm1  = (size_t)l * Dm * MLPD;
        const size_t oWm2  = (size_t)l * MLPD * Dm;
        const float* Al    = Aparam + (size_t)l * INNER;
        const float* stl = state + (size_t)l * Bsz * NSEG * INNER;

        gemm_mma<0, 0><<<dim3((2 * INNER) / 128, NROWS / 128, 1), 256>>>(
            xs, nullptr, winh + oWin, winl + oWin, ug, Dm, 0, 2 * INNER, 2 * INNER, Dm, 0);
        recurrence_k<<<(Bsz * NSEG * INNER) / 256, 256>>>(ug, Al, h, stl, SEGLEN);
        gemm_mma<1, 2><<<dim3(Dm / 128, NROWS / 128, 1), 256>>>(
            ug + INNER, h, wouth + oWout, woutl + oWout, xs, 2 * INNER, INNER, Dm, Dm, INNER, 0);
        gemm_mma<0, 1><<<dim3(MLPD / 128, NROWS / 128, 1), 256>>>(
            xs, nullptr, wm1h + oWm1, wm1l + oWm1, mlp, Dm, 0, MLPD, MLPD, Dm, 0);
        gemm_mma<0, 2><<<dim3(Dm / 128, NROWS / 128, 1), 256>>>(
            mlp, nullptr, wm2h + oWm2, wm2l + oWm2, xs, MLPD, 0, Dm, Dm, MLPD, 0);
    }

    extract_last_k<<<Bsz * NSEG, 128>>>(xs, last, starts, ends);
    head_k<<<(2 * Bsz * NSEG * Dm) / 256, 256>>>(last, muW, mub, lvW, lvb, out);
}